// round 1
// baseline (speedup 1.0000x reference)
#include <cuda_runtime.h>

// ---------------- device scratch (no allocation allowed) ----------------
__device__ float g_Qn[(size_t)16384 * 512];     // per-node Q projection
__device__ float g_den[16384 * 32];             // softmax denominators
__device__ float g_acc[16384 * 128];            // env numerator accumulators
__device__ float g_envnodes[16384 * 128];       // normalized env per node

static __device__ __forceinline__ float silu_f(float v) {
    return v / (1.0f + __expf(-v));
}

// ---------------- K1: Qn = node_attrs @ Wq  [16384,64]x[64,512] ----------------
__global__ void __launch_bounds__(256) k_qn(const float* __restrict__ A,
                                            const float* __restrict__ W,
                                            float* __restrict__ Qn) {
    __shared__ float sA[32][65];
    __shared__ float sB[64][128];
    const int rb = blockIdx.x * 32, cb = blockIdx.y * 128, t = threadIdx.x;
    for (int i = t; i < 32 * 64; i += 256)
        sA[i >> 6][i & 63] = A[(size_t)(rb + (i >> 6)) * 64 + (i & 63)];
    for (int i = t; i < 64 * 128; i += 256)
        sB[i >> 7][i & 127] = W[(size_t)(i >> 7) * 512 + cb + (i & 127)];
    __syncthreads();
    const int r0 = (t >> 5) * 4, c0 = (t & 31) * 4;
    float acc[4][4] = {};
#pragma unroll
    for (int k = 0; k < 64; k++) {
        float4 b = *(float4*)&sB[k][c0];
#pragma unroll
        for (int i = 0; i < 4; i++) {
            float a = sA[r0 + i][k];
            acc[i][0] += a * b.x; acc[i][1] += a * b.y;
            acc[i][2] += a * b.z; acc[i][3] += a * b.w;
        }
    }
#pragma unroll
    for (int i = 0; i < 4; i++)
        *(float4*)&Qn[(size_t)(rb + r0 + i) * 512 + cb + c0] =
            make_float4(acc[i][0], acc[i][1], acc[i][2], acc[i][3]);
}

// ---------------- K2: edge pass 1 (env MLP + logits + atomics) ----------------
struct SmemK2 {
    float x[32][97];     // [scalar(64) | cond(32)]
    float h[32][129];
    float w[32][64];
    float W[96 * 128];   // W1, then W2 (128x64), then Wk chunks (64x128)
    int   src[32];
};

__global__ void __launch_bounds__(256) k_edge1(
    const float* __restrict__ scal, const float* __restrict__ cond,
    const float* __restrict__ equiv, const float* __restrict__ W1,
    const float* __restrict__ b1, const float* __restrict__ W2,
    const float* __restrict__ Wk, const float* __restrict__ Qn,
    const int* __restrict__ src, float* __restrict__ den, float* __restrict__ acc)
{
    extern __shared__ char raw[];
    SmemK2& S = *reinterpret_cast<SmemK2*>(raw);
    const int t = threadIdx.x;
    const int e0 = blockIdx.x * 32;
    if (t < 32) S.src[t] = src[e0 + t];
    for (int i = t; i < 32 * 64; i += 256) {
        int e = i >> 6, j = i & 63;
        S.x[e][j] = scal[(size_t)(e0 + e) * 64 + j];
    }
    for (int i = t; i < 32 * 32; i += 256) {
        int e = i >> 5, j = i & 31;
        S.x[e][64 + j] = cond[(size_t)(e0 + e) * 32 + j];
    }
    for (int i = t; i < 96 * 128; i += 256) S.W[i] = W1[i];
    __syncthreads();

    const int e = t >> 3;
    // h = silu(x @ W1 + b1), each thread: 16 outputs of one edge
    {
        const int og = (t & 7) * 16;
        float a[16];
#pragma unroll
        for (int i = 0; i < 16; i++) a[i] = b1[og + i];
        for (int j = 0; j < 96; j++) {
            float xv = S.x[e][j];
            const float4* wr = (const float4*)&S.W[j * 128 + og];
#pragma unroll
            for (int q = 0; q < 4; q++) {
                float4 w4 = wr[q];
                a[4*q+0] += xv * w4.x; a[4*q+1] += xv * w4.y;
                a[4*q+2] += xv * w4.z; a[4*q+3] += xv * w4.w;
            }
        }
#pragma unroll
        for (int i = 0; i < 16; i++) S.h[e][og + i] = silu_f(a[i]);
    }
    __syncthreads();
    for (int i = t; i < 128 * 64; i += 256) S.W[i] = W2[i];
    __syncthreads();
    // w = h @ W2, each thread: 8 outputs
    {
        const int og = (t & 7) * 8;
        float a[8] = {};
        for (int j = 0; j < 128; j++) {
            float hv = S.h[e][j];
            const float4* wr = (const float4*)&S.W[j * 64 + og];
            float4 w4 = wr[0], w5 = wr[1];
            a[0] += hv * w4.x; a[1] += hv * w4.y; a[2] += hv * w4.z; a[3] += hv * w4.w;
            a[4] += hv * w5.x; a[5] += hv * w5.y; a[6] += hv * w5.z; a[7] += hv * w5.w;
        }
#pragma unroll
        for (int i = 0; i < 8; i++) S.w[e][og + i] = a[i];
    }
    const int sn = S.src[e];
    // logits per m-group of 8 (Wk chunk staged in smem), then exp + atomics
    for (int mg = 0; mg < 4; mg++) {
        __syncthreads();
        for (int i = t; i < 64 * 128; i += 256)
            S.W[i] = Wk[(size_t)(i >> 7) * 512 + mg * 128 + (i & 127)];
        __syncthreads();
        const int m = mg * 8 + (t & 7);
        float ka[16] = {};
        for (int j = 0; j < 64; j++) {
            float sv = S.x[e][j];
            const float4* wr = (const float4*)&S.W[j * 128 + (t & 7) * 16];
#pragma unroll
            for (int q = 0; q < 4; q++) {
                float4 w4 = wr[q];
                ka[4*q+0] += sv * w4.x; ka[4*q+1] += sv * w4.y;
                ka[4*q+2] += sv * w4.z; ka[4*q+3] += sv * w4.w;
            }
        }
        const float4* qp = (const float4*)&Qn[(size_t)sn * 512 + m * 16];
        float lg = 0.f;
#pragma unroll
        for (int q = 0; q < 4; q++) {
            float4 q4 = qp[q];
            lg += ka[4*q] * q4.x + ka[4*q+1] * q4.y + ka[4*q+2] * q4.z + ka[4*q+3] * q4.w;
        }
        lg *= 0.25f;                         // 1/sqrt(16)
        lg = fminf(5.0f, fmaxf(-5.0f, lg));  // CLIP
        float el = __expf(lg);               // max-subtraction unnecessary (clipped)
        atomicAdd(&den[(size_t)sn * 32 + m], el);
        float w0 = S.w[e][2 * m] * el;
        float w1 = S.w[e][2 * m + 1] * el;   // ENV_BLOCKS = (1,3)
        float4 ev = *(const float4*)&equiv[(size_t)(e0 + e) * 128 + m * 4];
        float* ap = &acc[(size_t)sn * 128 + 4 * m];
        atomicAdd(ap + 0, ev.x * w0);
        atomicAdd(ap + 1, ev.y * w1);
        atomicAdd(ap + 2, ev.z * w1);
        atomicAdd(ap + 3, ev.w * w1);
    }
}

// ---------------- K3: per-node finalize (softmax divide + SO3 layernorm) ----------------
__global__ void __launch_bounds__(128) k_node(const float* __restrict__ acc,
                                              const float* __restrict__ den,
                                              const float* __restrict__ genv,
                                              float* __restrict__ envn) {
    const int n = blockIdx.x * 4 + (threadIdx.x >> 5);
    const int m = threadIdx.x & 31;
    float d = den[(size_t)n * 32 + m];
    float inv = d > 0.f ? __frcp_rn(d) : 0.f;   // empty node -> 0 (never gathered)
    float4 a = *(const float4*)&acc[(size_t)n * 128 + 4 * m];
    float x0 = a.x * inv, x1 = a.y * inv, x2 = a.z * inv, x3 = a.w * inv;
    float s0 = x0 * x0;
    float s1 = x1 * x1 + x2 * x2 + x3 * x3;
#pragma unroll
    for (int o = 16; o; o >>= 1) {
        s0 += __shfl_xor_sync(0xffffffffu, s0, o);
        s1 += __shfl_xor_sync(0xffffffffu, s1, o);
    }
    float i0 = rsqrtf(s0 * (1.f / 32.f) + 1e-6f);
    float i1 = rsqrtf(s1 * (1.f / 96.f) + 1e-6f);
    float g0 = genv[2 * m], g1 = genv[2 * m + 1];
    *(float4*)&envn[(size_t)n * 128 + 4 * m] =
        make_float4(x0 * i0 * g0, x1 * i1 * g1, x2 * i1 * g1, x3 * i1 * g1);
}

// ---------------- K4: edge pass 2 (TP + LN + MLP + residual outputs) ----------------
struct SmemK4 {
    float env[32][132];   // gathered env_nodes; reused as pw (op cols 64..191)
    float eq[32][132];    // equiv_state tile
    float tp[32][264];    // tp_out, normalized in place
    float hp[32][129];
    float cnd[32][32];
    float W[128 * 96];    // Wp1 (96x128), then Wp2 column-chunks (128x96)
    float part[32][8][4];
    float ninv[32][4];
    int   src[32];
};

__global__ void __launch_bounds__(256) k_edge2(
    const float* __restrict__ scal, const float* __restrict__ cond,
    const float* __restrict__ equiv, const float* __restrict__ envn,
    const float* __restrict__ Wp1, const float* __restrict__ bp1,
    const float* __restrict__ Wp2, const float* __restrict__ gtp,
    const int* __restrict__ src, const float* __restrict__ ruc,
    float* __restrict__ outs, float* __restrict__ oute)
{
    extern __shared__ char raw[];
    SmemK4& S = *reinterpret_cast<SmemK4*>(raw);
    const int t = threadIdx.x;
    const int e0 = blockIdx.x * 32;
    if (t < 32) S.src[t] = src[e0 + t];
    __syncthreads();
    for (int i = t; i < 32 * 32; i += 256) {
        int e = i >> 5, j = i & 31;
        S.cnd[e][j] = cond[(size_t)(e0 + e) * 32 + j];
        *(float4*)&S.eq[e][4 * j]  = *(const float4*)&equiv[(size_t)(e0 + e) * 128 + 4 * j];
        *(float4*)&S.env[e][4 * j] = *(const float4*)&envn[(size_t)S.src[e] * 128 + 4 * j];
    }
    for (int i = t; i < 96 * 128; i += 256) S.W[i] = Wp1[i];
    __syncthreads();

    const int e = t >> 3;
    // tensor product + LN partial sums
    {
        float p0 = 0, p1 = 0, p2 = 0, p3 = 0;
#pragma unroll
        for (int i = 0; i < 4; i++) {
            int m = (t & 7) + 8 * i;
            float4 a = *(float4*)&S.eq[e][4 * m];
            float4 b = *(float4*)&S.env[e][4 * m];
            float o0 = a.x * b.x;
            float o1 = (a.y * b.y + a.z * b.z + a.w * b.w) * 0.57735026918962576f;
            float o2 = a.x * b.y, o3 = a.x * b.z, o4v = a.x * b.w;
            float o5 = a.y * b.x, o6 = a.z * b.x, o7 = a.w * b.x;
            float* tp = &S.tp[e][m * 8];
            tp[0] = o0; tp[1] = o1; tp[2] = o2; tp[3] = o3;
            tp[4] = o4v; tp[5] = o5; tp[6] = o6; tp[7] = o7;
            p0 += o0 * o0; p1 += o1 * o1;
            p2 += o2 * o2 + o3 * o3 + o4v * o4v;
            p3 += o5 * o5 + o6 * o6 + o7 * o7;
        }
        S.part[e][t & 7][0] = p0; S.part[e][t & 7][1] = p1;
        S.part[e][t & 7][2] = p2; S.part[e][t & 7][3] = p3;
    }
    __syncthreads();
    if (t < 128) {
        int ee = t >> 2, b = t & 3;
        float ss = 0.f;
#pragma unroll
        for (int i = 0; i < 8; i++) ss += S.part[ee][i][b];
        float cnt = (b < 2) ? 32.f : 96.f;  // TP_BLOCKS = (1,1,3,3)
        S.ninv[ee][b] = rsqrtf(ss / cnt + 1e-6f);
    }
    __syncthreads();
    // normalize tp in place (with g_tp)
    {
        float i0 = S.ninv[e][0], i1 = S.ninv[e][1], i2 = S.ninv[e][2], i3 = S.ninv[e][3];
#pragma unroll
        for (int i = 0; i < 4; i++) {
            int m = (t & 7) + 8 * i;
            float c0 = i0 * gtp[4 * m + 0], c1 = i1 * gtp[4 * m + 1];
            float c2 = i2 * gtp[4 * m + 2], c3 = i3 * gtp[4 * m + 3];
            float* tp = &S.tp[e][m * 8];
            tp[0] *= c0; tp[1] *= c1;
            tp[2] *= c2; tp[3] *= c2; tp[4] *= c2;
            tp[5] *= c3; tp[6] *= c3; tp[7] *= c3;
        }
    }
    __syncthreads();
    // hp = silu(xp @ Wp1 + bp1), xp = [scalars(64) | cond(32)]
    {
        const int og = (t & 7) * 16;
        float a[16];
#pragma unroll
        for (int i = 0; i < 16; i++) a[i] = bp1[og + i];
        for (int j = 0; j < 96; j++) {
            float xv = (j < 64) ? S.tp[e][(j >> 1) * 8 + (j & 1)] : S.cnd[e][j - 64];
            const float4* wr = (const float4*)&S.W[j * 128 + og];
#pragma unroll
            for (int q = 0; q < 4; q++) {
                float4 w4 = wr[q];
                a[4*q+0] += xv * w4.x; a[4*q+1] += xv * w4.y;
                a[4*q+2] += xv * w4.z; a[4*q+3] += xv * w4.w;
            }
        }
#pragma unroll
        for (int i = 0; i < 16; i++) S.hp[e][og + i] = silu_f(a[i]);
    }
    float r = ruc[0];
    float c_old = rsqrtf(r * r + 1.0f);
    float c_new = r * c_old;
    // op = hp @ Wp2, two 96-column chunks
    for (int ch = 0; ch < 2; ch++) {
        __syncthreads();
        for (int i = t; i < 128 * 96; i += 256)
            S.W[i] = Wp2[(size_t)(i / 96) * 192 + ch * 96 + (i % 96)];
        __syncthreads();
        const int cg = (t & 7) * 12;
        float a[12] = {};
        for (int j = 0; j < 128; j++) {
            float hv = S.hp[e][j];
            const float4* wr = (const float4*)&S.W[j * 96 + cg];
#pragma unroll
            for (int q = 0; q < 3; q++) {
                float4 w4 = wr[q];
                a[4*q+0] += hv * w4.x; a[4*q+1] += hv * w4.y;
                a[4*q+2] += hv * w4.z; a[4*q+3] += hv * w4.w;
            }
        }
#pragma unroll
        for (int i = 0; i < 12; i++) {
            int col = ch * 96 + cg + i;
            if (col < 64) {
                outs[(size_t)(e0 + e) * 64 + col] =
                    c_old * scal[(size_t)(e0 + e) * 64 + col] + c_new * a[i];
            } else {
                S.env[e][col - 64] = a[i];   // pw scratch (env no longer needed)
            }
        }
    }
    __syncthreads();
    // new_equiv + residual
    {
#pragma unroll
        for (int i = 0; i < 4; i++) {
            int m = (t & 7) + 8 * i;
            float pw0 = S.env[e][4 * m + 0], pw1 = S.env[e][4 * m + 1];
            float pw2 = S.env[e][4 * m + 2], pw3 = S.env[e][4 * m + 3];
            float* tp = &S.tp[e][m * 8];
            float ns  = pw0 * tp[0] + pw1 * tp[1];
            float nv0 = pw2 * tp[2] + pw3 * tp[5];
            float nv1 = pw2 * tp[3] + pw3 * tp[6];
            float nv2 = pw2 * tp[4] + pw3 * tp[7];
            float4 old = *(float4*)&S.eq[e][4 * m];
            *(float4*)&oute[(size_t)(e0 + e) * 128 + 4 * m] =
                make_float4(c_old * old.x + c_new * ns,
                            c_old * old.y + c_new * nv0,
                            c_old * old.z + c_new * nv1,
                            c_old * old.w + c_new * nv2);
        }
    }
}

// ---------------- launch ----------------
extern "C" void kernel_launch(void* const* d_in, const int* in_sizes, int n_in,
                              void* d_out, int out_size) {
    const float* node_attrs = (const float*)d_in[0];
    const float* scal  = (const float*)d_in[1];
    const float* equiv = (const float*)d_in[2];
    const float* cond  = (const float*)d_in[3];
    const float* ruc   = (const float*)d_in[4];
    const float* W1    = (const float*)d_in[5];
    const float* b1    = (const float*)d_in[6];
    const float* W2    = (const float*)d_in[7];
    const float* Wq    = (const float*)d_in[8];
    const float* Wk    = (const float*)d_in[9];
    const float* genv  = (const float*)d_in[10];
    const float* gtp   = (const float*)d_in[11];
    const float* Wp1   = (const float*)d_in[12];
    const float* bp1   = (const float*)d_in[13];
    const float* Wp2   = (const float*)d_in[14];
    const int*   src   = (const int*)d_in[15];

    const int N = in_sizes[0] / 64;
    const int E = in_sizes[1] / 64;
    float* outs = (float*)d_out;
    float* oute = outs + (size_t)E * 64;

    float *pQn, *pden, *pacc, *penv;
    cudaGetSymbolAddress((void**)&pQn,  g_Qn);
    cudaGetSymbolAddress((void**)&pden, g_den);
    cudaGetSymbolAddress((void**)&pacc, g_acc);
    cudaGetSymbolAddress((void**)&penv, g_envnodes);

    cudaFuncSetAttribute(k_edge1, cudaFuncAttributeMaxDynamicSharedMemorySize, (int)sizeof(SmemK2));
    cudaFuncSetAttribute(k_edge2, cudaFuncAttributeMaxDynamicSharedMemorySize, (int)sizeof(SmemK4));

    cudaMemsetAsync(pden, 0, (size_t)N * 32 * sizeof(float));
    cudaMemsetAsync(pacc, 0, (size_t)N * 128 * sizeof(float));

    k_qn<<<dim3(N / 32, 4), 256>>>(node_attrs, Wq, pQn);
    k_edge1<<<E / 32, 256, sizeof(SmemK2)>>>(scal, cond, equiv, W1, b1, W2, Wk, pQn, src, pden, pacc);
    k_node<<<N / 4, 128>>>(pacc, pden, genv, penv);
    k_edge2<<<E / 32, 256, sizeof(SmemK4)>>>(scal, cond, equiv, penv, Wp1, bp1, Wp2, gtp, src, ruc, outs, oute);
}

// round 2
// speedup vs baseline: 4.7138x; 4.7138x over previous
#include <cuda_runtime.h>

// ---------------- fixed problem shape ----------------
#define E_TOT 262144
#define N_TOT 16384

// ---------------- device scratch (static, no allocation) ----------------
__device__ float g_Qn  [(size_t)N_TOT * 512];
__device__ float g_den [(size_t)N_TOT * 32];
__device__ float g_accm[(size_t)N_TOT * 128];
__device__ float g_envn[(size_t)N_TOT * 128];
__device__ float g_H   [(size_t)E_TOT * 128];
__device__ float g_We  [(size_t)E_TOT * 64];
__device__ float g_tpo [(size_t)E_TOT * 256];
__device__ float g_s2  [(size_t)E_TOT * 64];

typedef unsigned long long u64;

static __device__ __forceinline__ u64 dup2(float a) {
    u64 r; asm("mov.b64 %0, {%1, %1};" : "=l"(r) : "f"(a)); return r;
}
static __device__ __forceinline__ void fma2(u64& acc, u64 a, u64 b) {
    asm("fma.rn.f32x2 %0, %1, %2, %0;" : "+l"(acc) : "l"(a), "l"(b));
}
static __device__ __forceinline__ float lo2(u64 v) { return __uint_as_float((unsigned)v); }
static __device__ __forceinline__ float hi2(u64 v) { return __uint_as_float((unsigned)(v >> 32)); }
static __device__ __forceinline__ float silu_f(float v) { return v / (1.0f + __expf(-v)); }

// ---------------- K1: Qn = node_attrs @ Wq  [16384,64]x[64,512] ----------------
__global__ void __launch_bounds__(256) k_qn(const float* __restrict__ A,
                                            const float* __restrict__ W,
                                            float* __restrict__ Qn) {
    __shared__ float sA[32][65];
    __shared__ float sB[64][128];
    const int rb = blockIdx.x * 32, cb = blockIdx.y * 128, t = threadIdx.x;
    for (int i = t; i < 32 * 64; i += 256)
        sA[i >> 6][i & 63] = A[(size_t)(rb + (i >> 6)) * 64 + (i & 63)];
    for (int i = t; i < 64 * 128; i += 256)
        sB[i >> 7][i & 127] = W[(size_t)(i >> 7) * 512 + cb + (i & 127)];
    __syncthreads();
    const int r0 = (t >> 5) * 4, c0 = (t & 31) * 4;
    float acc[4][4] = {};
#pragma unroll
    for (int k = 0; k < 64; k++) {
        float4 b = *(float4*)&sB[k][c0];
#pragma unroll
        for (int i = 0; i < 4; i++) {
            float a = sA[r0 + i][k];
            acc[i][0] += a * b.x; acc[i][1] += a * b.y;
            acc[i][2] += a * b.z; acc[i][3] += a * b.w;
        }
    }
#pragma unroll
    for (int i = 0; i < 4; i++)
        *(float4*)&Qn[(size_t)(rb + r0 + i) * 512 + cb + c0] =
            make_float4(acc[i][0], acc[i][1], acc[i][2], acc[i][3]);
}

// ---------------- GEMM A: out = silu([X64|C32] @ W + b)   [E,96]x[96,128] ----------------
// BM=128, BN=128, K=96, 256 threads, thread tile 8x8 (f32x2 packed)
__global__ void __launch_bounds__(256) g_mlp96(const float* __restrict__ X64,
                                               const float* __restrict__ C32,
                                               const float* __restrict__ W,
                                               const float* __restrict__ bias,
                                               float* __restrict__ out) {
    extern __shared__ float sm[];
    float (*As)[132] = (float(*)[132])sm;                 // [96][132]
    float (*Bs)[132] = (float(*)[132])(sm + 96 * 132);    // [96][132]
    const int t = threadIdx.x;
    const size_t e0 = (size_t)blockIdx.x * 128;
    for (int i = t; i < 96 * 32; i += 256) {
        int k = i >> 5, c = (i & 31) * 4;
        *(float4*)&Bs[k][c] = *(const float4*)&W[k * 128 + c];
    }
    for (int i = t; i < 128 * 16; i += 256) {
        int r = i >> 4, k = (i & 15) * 4;
        float4 v = *(const float4*)&X64[(e0 + r) * 64 + k];
        As[k][r] = v.x; As[k + 1][r] = v.y; As[k + 2][r] = v.z; As[k + 3][r] = v.w;
    }
    for (int i = t; i < 128 * 8; i += 256) {
        int r = i >> 3, k = (i & 7) * 4;
        float4 v = *(const float4*)&C32[(e0 + r) * 32 + k];
        As[64 + k][r] = v.x; As[65 + k][r] = v.y; As[66 + k][r] = v.z; As[67 + k][r] = v.w;
    }
    __syncthreads();
    const int tx = t & 15, ty = t >> 4;
    const int c0 = tx * 8, r0 = ty * 8;
    u64 acc[8][4];
#pragma unroll
    for (int i = 0; i < 8; i++)
#pragma unroll
        for (int j = 0; j < 4; j++) acc[i][j] = 0ull;
#pragma unroll 4
    for (int k = 0; k < 96; k++) {
        float4 a0 = *(float4*)&As[k][r0], a1 = *(float4*)&As[k][r0 + 4];
        ulonglong2 b0 = *(ulonglong2*)&Bs[k][c0];
        ulonglong2 b1 = *(ulonglong2*)&Bs[k][c0 + 4];
        float av[8] = {a0.x, a0.y, a0.z, a0.w, a1.x, a1.y, a1.z, a1.w};
#pragma unroll
        for (int i = 0; i < 8; i++) {
            u64 ad = dup2(av[i]);
            fma2(acc[i][0], ad, b0.x); fma2(acc[i][1], ad, b0.y);
            fma2(acc[i][2], ad, b1.x); fma2(acc[i][3], ad, b1.y);
        }
    }
    float bb[8];
#pragma unroll
    for (int j = 0; j < 8; j++) bb[j] = bias[c0 + j];
#pragma unroll
    for (int i = 0; i < 8; i++) {
        float o[8];
#pragma unroll
        for (int j = 0; j < 4; j++) {
            o[2 * j]     = silu_f(lo2(acc[i][j]) + bb[2 * j]);
            o[2 * j + 1] = silu_f(hi2(acc[i][j]) + bb[2 * j + 1]);
        }
        size_t e = e0 + r0 + i;
        *(float4*)&out[e * 128 + c0]     = make_float4(o[0], o[1], o[2], o[3]);
        *(float4*)&out[e * 128 + c0 + 4] = make_float4(o[4], o[5], o[6], o[7]);
    }
}

// ---------------- GEMM B: We = H @ W2   [E,128]x[128,64] ----------------
// BM=128, BN=64, K=128, 128 threads, tile 8x8
__global__ void __launch_bounds__(128) g_mlp2k(const float* __restrict__ H,
                                               const float* __restrict__ W,
                                               float* __restrict__ out) {
    extern __shared__ float sm[];
    float (*As)[132] = (float(*)[132])sm;                 // [128][132]
    float (*Bs)[68]  = (float(*)[68])(sm + 128 * 132);    // [128][68]
    const int t = threadIdx.x;
    const size_t e0 = (size_t)blockIdx.x * 128;
    for (int i = t; i < 128 * 16; i += 128) {
        int k = i >> 4, c = (i & 15) * 4;
        *(float4*)&Bs[k][c] = *(const float4*)&W[k * 64 + c];
    }
    for (int i = t; i < 128 * 32; i += 128) {
        int r = i >> 5, k = (i & 31) * 4;
        float4 v = *(const float4*)&H[(e0 + r) * 128 + k];
        As[k][r] = v.x; As[k + 1][r] = v.y; As[k + 2][r] = v.z; As[k + 3][r] = v.w;
    }
    __syncthreads();
    const int tx = t & 7, ty = t >> 3;
    const int c0 = tx * 8, r0 = ty * 8;
    u64 acc[8][4];
#pragma unroll
    for (int i = 0; i < 8; i++)
#pragma unroll
        for (int j = 0; j < 4; j++) acc[i][j] = 0ull;
#pragma unroll 4
    for (int k = 0; k < 128; k++) {
        float4 a0 = *(float4*)&As[k][r0], a1 = *(float4*)&As[k][r0 + 4];
        ulonglong2 b0 = *(ulonglong2*)&Bs[k][c0];
        ulonglong2 b1 = *(ulonglong2*)&Bs[k][c0 + 4];
        float av[8] = {a0.x, a0.y, a0.z, a0.w, a1.x, a1.y, a1.z, a1.w};
#pragma unroll
        for (int i = 0; i < 8; i++) {
            u64 ad = dup2(av[i]);
            fma2(acc[i][0], ad, b0.x); fma2(acc[i][1], ad, b0.y);
            fma2(acc[i][2], ad, b1.x); fma2(acc[i][3], ad, b1.y);
        }
    }
#pragma unroll
    for (int i = 0; i < 8; i++) {
        size_t e = e0 + r0 + i;
        *(float4*)&out[e * 64 + c0] =
            make_float4(lo2(acc[i][0]), hi2(acc[i][0]), lo2(acc[i][1]), hi2(acc[i][1]));
        *(float4*)&out[e * 64 + c0 + 4] =
            make_float4(lo2(acc[i][2]), hi2(acc[i][2]), lo2(acc[i][3]), hi2(acc[i][3]));
    }
}

// ---------------- GEMM C: K = scal @ Wk chunk + fused logits/exp/atomics ----------------
// BM=128, BN=128, K=64, 256 threads, grid.y = 4 column chunks
__global__ void __launch_bounds__(256) g_kqk(const float* __restrict__ scal,
                                             const float* __restrict__ Wk,
                                             const float* __restrict__ Qn,
                                             const float* __restrict__ We,
                                             const float* __restrict__ equiv,
                                             const int* __restrict__ src,
                                             float* __restrict__ den,
                                             float* __restrict__ accg) {
    extern __shared__ float sm[];
    float (*As)[132] = (float(*)[132])sm;                 // [64][132]
    float (*Bs)[132] = (float(*)[132])(sm + 64 * 132);    // [64][132]
    int* s_src = (int*)(sm + 2 * 64 * 132);
    const int t = threadIdx.x;
    const size_t e0 = (size_t)blockIdx.x * 128;
    const int cb = blockIdx.y * 128;
    if (t < 128) s_src[t] = src[e0 + t];
    for (int i = t; i < 64 * 32; i += 256) {
        int k = i >> 5, c = (i & 31) * 4;
        *(float4*)&Bs[k][c] = *(const float4*)&Wk[(size_t)k * 512 + cb + c];
    }
    for (int i = t; i < 128 * 16; i += 256) {
        int r = i >> 4, k = (i & 15) * 4;
        float4 v = *(const float4*)&scal[(e0 + r) * 64 + k];
        As[k][r] = v.x; As[k + 1][r] = v.y; As[k + 2][r] = v.z; As[k + 3][r] = v.w;
    }
    __syncthreads();
    const int tx = t & 15, ty = t >> 4;
    const int c0 = tx * 8, r0 = ty * 8;
    u64 acc[8][4];
#pragma unroll
    for (int i = 0; i < 8; i++)
#pragma unroll
        for (int j = 0; j < 4; j++) acc[i][j] = 0ull;
#pragma unroll 4
    for (int k = 0; k < 64; k++) {
        float4 a0 = *(float4*)&As[k][r0], a1 = *(float4*)&As[k][r0 + 4];
        ulonglong2 b0 = *(ulonglong2*)&Bs[k][c0];
        ulonglong2 b1 = *(ulonglong2*)&Bs[k][c0 + 4];
        float av[8] = {a0.x, a0.y, a0.z, a0.w, a1.x, a1.y, a1.z, a1.w};
#pragma unroll
        for (int i = 0; i < 8; i++) {
            u64 ad = dup2(av[i]);
            fma2(acc[i][0], ad, b0.x); fma2(acc[i][1], ad, b0.y);
            fma2(acc[i][2], ad, b1.x); fma2(acc[i][3], ad, b1.y);
        }
    }
    const int m = (cb + c0) >> 4;   // head index for even-tx threads
#pragma unroll
    for (int i = 0; i < 8; i++) {
        const int sn = s_src[r0 + i];
        const size_t e = e0 + r0 + i;
        const float4* qp = (const float4*)&Qn[(size_t)sn * 512 + cb + c0];
        float4 q0 = qp[0], q1 = qp[1];
        float part = lo2(acc[i][0]) * q0.x + hi2(acc[i][0]) * q0.y
                   + lo2(acc[i][1]) * q0.z + hi2(acc[i][1]) * q0.w
                   + lo2(acc[i][2]) * q1.x + hi2(acc[i][2]) * q1.y
                   + lo2(acc[i][3]) * q1.z + hi2(acc[i][3]) * q1.w;
        float other = __shfl_xor_sync(0xffffffffu, part, 1);
        if (!(tx & 1)) {
            float lg = (part + other) * 0.25f;          // 1/sqrt(16)
            lg = fminf(5.0f, fmaxf(-5.0f, lg));         // CLIP
            float el = __expf(lg);                      // no max-shift needed (clipped)
            atomicAdd(&den[(size_t)sn * 32 + m], el);
            float w0 = We[e * 64 + 2 * m] * el;
            float w1 = We[e * 64 + 2 * m + 1] * el;     // ENV_BLOCKS = (1,3)
            float4 ev = *(const float4*)&equiv[e * 128 + 4 * m];
            float* ap = &accg[(size_t)sn * 128 + 4 * m];
            atomicAdd(ap + 0, ev.x * w0);
            atomicAdd(ap + 1, ev.y * w1);
            atomicAdd(ap + 2, ev.z * w1);
            atomicAdd(ap + 3, ev.w * w1);
        }
    }
}

// ---------------- node finalize (softmax divide + SO3 layernorm) ----------------
__global__ void __launch_bounds__(128) k_node(const float* __restrict__ acc,
                                              const float* __restrict__ den,
                                              const float* __restrict__ genv,
                                              float* __restrict__ envn) {
    const int n = blockIdx.x * 4 + (threadIdx.x >> 5);
    const int m = threadIdx.x & 31;
    float d = den[(size_t)n * 32 + m];
    float inv = d > 0.f ? __frcp_rn(d) : 0.f;
    float4 a = *(const float4*)&acc[(size_t)n * 128 + 4 * m];
    float x0 = a.x * inv, x1 = a.y * inv, x2 = a.z * inv, x3 = a.w * inv;
    float s0 = x0 * x0;
    float s1 = x1 * x1 + x2 * x2 + x3 * x3;
#pragma unroll
    for (int o = 16; o; o >>= 1) {
        s0 += __shfl_xor_sync(0xffffffffu, s0, o);
        s1 += __shfl_xor_sync(0xffffffffu, s1, o);
    }
    float i0 = rsqrtf(s0 * (1.f / 32.f) + 1e-6f);
    float i1 = rsqrtf(s1 * (1.f / 96.f) + 1e-6f);
    float g0 = genv[2 * m], g1 = genv[2 * m + 1];
    *(float4*)&envn[(size_t)n * 128 + 4 * m] =
        make_float4(x0 * i0 * g0, x1 * i1 * g1, x2 * i1 * g1, x3 * i1 * g1);
}

// ---------------- tensor product + SO3 layernorm per edge (warp per edge) ----------------
__global__ void __launch_bounds__(256) k_tp(const float* __restrict__ equiv,
                                            const float* __restrict__ envn,
                                            const int* __restrict__ src,
                                            const float* __restrict__ gtp,
                                            float* __restrict__ tpo,
                                            float* __restrict__ s2) {
    const size_t e = (size_t)blockIdx.x * 8 + (threadIdx.x >> 5);
    const int m = threadIdx.x & 31;
    const int sn = src[e];
    float4 a = *(const float4*)&equiv[e * 128 + 4 * m];
    float4 b = *(const float4*)&envn[(size_t)sn * 128 + 4 * m];
    float o0 = a.x * b.x;
    float o1 = (a.y * b.y + a.z * b.z + a.w * b.w) * 0.57735026918962576f;
    float o2 = a.x * b.y, o3 = a.x * b.z, o4 = a.x * b.w;
    float o5 = a.y * b.x, o6 = a.z * b.x, o7 = a.w * b.x;
    float p0 = o0 * o0, p1 = o1 * o1;
    float p2 = o2 * o2 + o3 * o3 + o4 * o4;
    float p3 = o5 * o5 + o6 * o6 + o7 * o7;
#pragma unroll
    for (int o = 16; o; o >>= 1) {
        p0 += __shfl_xor_sync(0xffffffffu, p0, o);
        p1 += __shfl_xor_sync(0xffffffffu, p1, o);
        p2 += __shfl_xor_sync(0xffffffffu, p2, o);
        p3 += __shfl_xor_sync(0xffffffffu, p3, o);
    }
    float c0 = rsqrtf(p0 * (1.f / 32.f) + 1e-6f) * gtp[4 * m + 0];
    float c1 = rsqrtf(p1 * (1.f / 32.f) + 1e-6f) * gtp[4 * m + 1];
    float c2 = rsqrtf(p2 * (1.f / 96.f) + 1e-6f) * gtp[4 * m + 2];
    float c3 = rsqrtf(p3 * (1.f / 96.f) + 1e-6f) * gtp[4 * m + 3];
    o0 *= c0; o1 *= c1; o2 *= c2; o3 *= c2; o4 *= c2; o5 *= c3; o6 *= c3; o7 *= c3;
    *(float4*)&tpo[e * 256 + m * 8]     = make_float4(o0, o1, o2, o3);
    *(float4*)&tpo[e * 256 + m * 8 + 4] = make_float4(o4, o5, o6, o7);
    *(float2*)&s2[e * 64 + 2 * m] = make_float2(o0, o1);
}

// ---------------- GEMM D: op = H @ Wp2 chunk + fused residual outputs ----------------
// BM=128, BN=64, K=128, 128 threads, grid.y = 3 chunks (192 cols)
__global__ void __launch_bounds__(128) g_mlp4k(const float* __restrict__ H,
                                               const float* __restrict__ W,
                                               const float* __restrict__ scal,
                                               const float* __restrict__ equiv,
                                               const float* __restrict__ tpo,
                                               const float* __restrict__ ruc,
                                               float* __restrict__ outs,
                                               float* __restrict__ oute) {
    extern __shared__ float sm[];
    float (*As)[132] = (float(*)[132])sm;                 // [128][132]
    float (*Bs)[68]  = (float(*)[68])(sm + 128 * 132);    // [128][68]
    const int t = threadIdx.x;
    const size_t e0 = (size_t)blockIdx.x * 128;
    const int cb = blockIdx.y * 64;
    for (int i = t; i < 128 * 16; i += 128) {
        int k = i >> 4, c = (i & 15) * 4;
        *(float4*)&Bs[k][c] = *(const float4*)&W[(size_t)k * 192 + cb + c];
    }
    for (int i = t; i < 128 * 32; i += 128) {
        int r = i >> 5, k = (i & 31) * 4;
        float4 v = *(const float4*)&H[(e0 + r) * 128 + k];
        As[k][r] = v.x; As[k + 1][r] = v.y; As[k + 2][r] = v.z; As[k + 3][r] = v.w;
    }
    __syncthreads();
    const int tx = t & 7, ty = t >> 3;
    const int c0 = tx * 8, r0 = ty * 8;
    u64 acc[8][4];
#pragma unroll
    for (int i = 0; i < 8; i++)
#pragma unroll
        for (int j = 0; j < 4; j++) acc[i][j] = 0ull;
#pragma unroll 4
    for (int k = 0; k < 128; k++) {
        float4 a0 = *(float4*)&As[k][r0], a1 = *(float4*)&As[k][r0 + 4];
        ulonglong2 b0 = *(ulonglong2*)&Bs[k][c0];
        ulonglong2 b1 = *(ulonglong2*)&Bs[k][c0 + 4];
        float av[8] = {a0.x, a0.y, a0.z, a0.w, a1.x, a1.y, a1.z, a1.w};
#pragma unroll
        for (int i = 0; i < 8; i++) {
            u64 ad = dup2(av[i]);
            fma2(acc[i][0], ad, b0.x); fma2(acc[i][1], ad, b0.y);
            fma2(acc[i][2], ad, b1.x); fma2(acc[i][3], ad, b1.y);
        }
    }
    float r = ruc[0];
    float c_old = rsqrtf(r * r + 1.0f);
    float c_new = r * c_old;
    if (cb == 0) {
        // new_scalar residual: cols 0..63 of op
#pragma unroll
        for (int i = 0; i < 8; i++) {
            size_t e = e0 + r0 + i;
            float4 s0 = *(const float4*)&scal[e * 64 + c0];
            float4 s1 = *(const float4*)&scal[e * 64 + c0 + 4];
            *(float4*)&outs[e * 64 + c0] = make_float4(
                c_old * s0.x + c_new * lo2(acc[i][0]),
                c_old * s0.y + c_new * hi2(acc[i][0]),
                c_old * s0.z + c_new * lo2(acc[i][1]),
                c_old * s0.w + c_new * hi2(acc[i][1]));
            *(float4*)&outs[e * 64 + c0 + 4] = make_float4(
                c_old * s1.x + c_new * lo2(acc[i][2]),
                c_old * s1.y + c_new * hi2(acc[i][2]),
                c_old * s1.z + c_new * lo2(acc[i][3]),
                c_old * s1.w + c_new * hi2(acc[i][3]));
        }
    } else {
        // pw path: cols cb+c0 .. +7 -> 2 irrep channels
        const int m0 = (cb + c0 - 64) >> 2;
#pragma unroll
        for (int i = 0; i < 8; i++) {
            size_t e = e0 + r0 + i;
#pragma unroll
            for (int s = 0; s < 2; s++) {
                int mm = m0 + s;
                float pw0 = lo2(acc[i][2 * s]),     pw1 = hi2(acc[i][2 * s]);
                float pw2 = lo2(acc[i][2 * s + 1]), pw3 = hi2(acc[i][2 * s + 1]);
                const float4* tp = (const float4*)&tpo[e * 256 + mm * 8];
                float4 t0 = tp[0], t1 = tp[1];
                float ns  = pw0 * t0.x + pw1 * t0.y;
                float nv0 = pw2 * t0.z + pw3 * t1.y;
                float nv1 = pw2 * t0.w + pw3 * t1.z;
                float nv2 = pw2 * t1.x + pw3 * t1.w;
                float4 old = *(const float4*)&equiv[e * 128 + 4 * mm];
                *(float4*)&oute[e * 128 + 4 * mm] = make_float4(
                    c_old * old.x + c_new * ns,
                    c_old * old.y + c_new * nv0,
                    c_old * old.z + c_new * nv1,
                    c_old * old.w + c_new * nv2);
            }
        }
    }
}

// ---------------- launch ----------------
extern "C" void kernel_launch(void* const* d_in, const int* in_sizes, int n_in,
                              void* d_out, int out_size) {
    const float* node_attrs = (const float*)d_in[0];
    const float* scal  = (const float*)d_in[1];
    const float* equiv = (const float*)d_in[2];
    const float* cond  = (const float*)d_in[3];
    const float* ruc   = (const float*)d_in[4];
    const float* W1    = (const float*)d_in[5];
    const float* b1    = (const float*)d_in[6];
    const float* W2    = (const float*)d_in[7];
    const float* Wq    = (const float*)d_in[8];
    const float* Wk    = (const float*)d_in[9];
    const float* genv  = (const float*)d_in[10];
    const float* gtp   = (const float*)d_in[11];
    const float* Wp1   = (const float*)d_in[12];
    const float* bp1   = (const float*)d_in[13];
    const float* Wp2   = (const float*)d_in[14];
    const int*   src   = (const int*)d_in[15];

    const int N = in_sizes[0] / 64;
    const int E = in_sizes[1] / 64;
    float* outs = (float*)d_out;
    float* oute = outs + (size_t)E * 64;

    float *pQn, *pden, *pacc, *penv, *pH, *pWe, *ptpo, *ps2;
    cudaGetSymbolAddress((void**)&pQn,  g_Qn);
    cudaGetSymbolAddress((void**)&pden, g_den);
    cudaGetSymbolAddress((void**)&pacc, g_accm);
    cudaGetSymbolAddress((void**)&penv, g_envn);
    cudaGetSymbolAddress((void**)&pH,   g_H);
    cudaGetSymbolAddress((void**)&pWe,  g_We);
    cudaGetSymbolAddress((void**)&ptpo, g_tpo);
    cudaGetSymbolAddress((void**)&ps2,  g_s2);

    const int SM1 = (96 * 132 + 96 * 132) * 4;              // 101376
    const int SM2 = (128 * 132 + 128 * 68) * 4;             // 102400
    const int SMK = (64 * 132 * 2) * 4 + 128 * 4;           // 68096

    cudaFuncSetAttribute(g_mlp96, cudaFuncAttributeMaxDynamicSharedMemorySize, SM1);
    cudaFuncSetAttribute(g_mlp2k, cudaFuncAttributeMaxDynamicSharedMemorySize, SM2);
    cudaFuncSetAttribute(g_kqk,   cudaFuncAttributeMaxDynamicSharedMemorySize, SMK);
    cudaFuncSetAttribute(g_mlp4k, cudaFuncAttributeMaxDynamicSharedMemorySize, SM2);

    cudaMemsetAsync(pden, 0, (size_t)N * 32 * sizeof(float));
    cudaMemsetAsync(pacc, 0, (size_t)N * 128 * sizeof(float));

    k_qn<<<dim3(N / 32, 4), 256>>>(node_attrs, Wq, pQn);
    g_mlp96<<<E / 128, 256, SM1>>>(scal, cond, W1, b1, pH);
    g_mlp2k<<<E / 128, 128, SM2>>>(pH, W2, pWe);
    g_kqk<<<dim3(E / 128, 4), 256, SMK>>>(scal, Wk, pQn, pWe, equiv, src, pden, pacc);
    k_node<<<N / 4, 128>>>(pacc, pden, genv, penv);
    k_tp<<<E / 8, 256>>>(equiv, penv, src, gtp, ptpo, ps2);
    g_mlp96<<<E / 128, 256, SM1>>>(ps2, cond, Wp1, bp1, pH);
    g_mlp4k<<<dim3(E / 128, 3), 128, SM2>>>(pH, Wp2, scal, equiv, ptpo, ruc, outs, oute);
}